// round 16
// baseline (speedup 1.0000x reference)
#include <cuda_runtime.h>

#define ROWS 48
#define ROW_ELEMS (512 * 512)                  // 262144 elements per (b,c) row
#define CHUNKS 32
#define CHUNK_ELEMS (ROW_ELEMS / CHUNKS)       // 8192
#define THREADS 256
#define VEC_PER_THREAD (CHUNK_ELEMS / 4 / THREADS)  // 8 float4 per thread (minmax)
#define V8_PER_THREAD (CHUNK_ELEMS / 8 / THREADS)   // 4 float8 per thread (quantize)

// Per-(row,chunk) partial min/max. Every slot is written unconditionally by
// minmax_kernel on every call -> no init kernel, no atomics, deterministic.
__device__ float g_pmin[ROWS][CHUNKS];
__device__ float g_pmax[ROWS][CHUNKS];

__global__ void __launch_bounds__(THREADS) minmax_kernel(const float4* __restrict__ in) {
    const int row = blockIdx.y;
    const int chunk = blockIdx.x;
    const long base4 = (long)row * (ROW_ELEMS / 4) + (long)chunk * (CHUNK_ELEMS / 4);
    const int tid = threadIdx.x;

    float mn = 3.402823466e+38f;
    float mx = -3.402823466e+38f;

#pragma unroll
    for (int k = 0; k < VEC_PER_THREAD; k++) {
        float4 v = in[base4 + k * THREADS + tid];
        mn = fminf(mn, fminf(fminf(v.x, v.y), fminf(v.z, v.w)));
        mx = fmaxf(mx, fmaxf(fmaxf(v.x, v.y), fmaxf(v.z, v.w)));
    }

#pragma unroll
    for (int o = 16; o > 0; o >>= 1) {
        mn = fminf(mn, __shfl_xor_sync(0xffffffffu, mn, o));
        mx = fmaxf(mx, __shfl_xor_sync(0xffffffffu, mx, o));
    }

    __shared__ float smn[THREADS / 32];
    __shared__ float smx[THREADS / 32];
    if ((tid & 31) == 0) {
        smn[tid >> 5] = mn;
        smx[tid >> 5] = mx;
    }
    __syncthreads();

    if (tid == 0) {
        float bmn = smn[0], bmx = smx[0];
#pragma unroll
        for (int w = 1; w < THREADS / 32; w++) {
            bmn = fminf(bmn, smn[w]);
            bmx = fmaxf(bmx, smx[w]);
        }
        g_pmin[row][chunk] = bmn;
        g_pmax[row][chunk] = bmx;
    }
}

// Reference-exact bound: b_j = fl32( mn + fl32( d * (j/16) ) ), j/16 exact.
// Exact-rounding intrinsics block fma contraction (must match JAX bit-for-bit).
__device__ __forceinline__ float bound_j(float mn, float d, int j) {
    return __fadd_rn(mn, __fmul_rn(d, (float)j * 0.0625f));
}
// Reference-exact mid: m_j = fl32( 0.5 * fl32( b_j + b_{j+1} ) ).
__device__ __forceinline__ float mid_j(float mn, float d, int j) {
    return __fmul_rn(0.5f, __fadd_rn(bound_j(mn, d, j), bound_j(mn, d, j + 1)));
}

// 256-bit global load (sm_100a): 8 floats in one LDG.
__device__ __forceinline__ void ldg256(const float* p, float* a) {
    asm volatile("ld.global.nc.v8.f32 {%0,%1,%2,%3,%4,%5,%6,%7}, [%8];"
                 : "=f"(a[0]), "=f"(a[1]), "=f"(a[2]), "=f"(a[3]),
                   "=f"(a[4]), "=f"(a[5]), "=f"(a[6]), "=f"(a[7])
                 : "l"(p));
}
// 256-bit streaming store (evict-first: output is write-once, keep input in L2).
__device__ __forceinline__ void stg256_cs(float* p, const float* a) {
    asm volatile("st.global.cs.v8.f32 [%0], {%1,%2,%3,%4,%5,%6,%7,%8};"
                 :: "l"(p),
                    "f"(a[0]), "f"(a[1]), "f"(a[2]), "f"(a[3]),
                    "f"(a[4]), "f"(a[5]), "f"(a[6]), "f"(a[7])
                 : "memory");
}

__global__ void __launch_bounds__(THREADS) quantize_kernel(const float* __restrict__ in,
                                                           float* __restrict__ out) {
    const int row = blockIdx.y;
    const int chunk = blockIdx.x;
    // Base in float elements; each thread handles V8_PER_THREAD 8-float tiles.
    const long base = (long)row * ROW_ELEMS + (long)chunk * CHUNK_ELEMS;
    const int tid = threadIdx.x;
    const int lane = tid & 31;

    // One warp reduces the 32 partials; broadcast via 2 smem floats.
    __shared__ float s_mn, s_mx;
    if (tid < 32) {
        float v1 = g_pmin[row][tid];
        float v2 = g_pmax[row][tid];
#pragma unroll
        for (int o = 16; o > 0; o >>= 1) {
            v1 = fminf(v1, __shfl_xor_sync(0xffffffffu, v1, o));
            v2 = fmaxf(v2, __shfl_xor_sync(0xffffffffu, v2, o));
        }
        if (tid == 0) { s_mn = v1; s_mx = v2; }
    }
    __syncthreads();

    const float mn = s_mn;
    const float mx = s_mx;
    const float d = __fadd_rn(mx, -mn);  // mx >= mn

    // Degenerate test, matching float32 reference arithmetic:
    // robust_eps = 4 * FLT_EPSILON; deg = d <= robust_eps + 1e-5 * |mx|
    const float thresh = __fadd_rn(4.76837158203125e-07f, __fmul_rn(1e-5f, fabsf(mx)));
    if (d <= thresh) {
        float q[8];
#pragma unroll
        for (int e = 0; e < 8; e++) q[e] = mn;
#pragma unroll
        for (int k = 0; k < V8_PER_THREAD; k++) {
            stg256_cs(out + base + (long)(k * THREADS + tid) * 8, q);
        }
        return;
    }

    // Warp-register tables (R14 scheme, best measured): lane L holds b_L and m_L.
    //   b_L = bound_L for L<=15, +INF for L>=16  (idx=16 -> probe INF -> r=15)
    //   m_L = mid_L   for L<=15
    const float b_lane = (lane <= 15) ? bound_j(mn, d, lane)
                                      : __int_as_float(0x7f800000);
    const float m_lane = mid_j(mn, d, (lane <= 15) ? lane : 15);

    const float scale = 16.0f / d;
    const float bias = __fmaf_rn(-mn, scale, 0.5f);  // (x-mn)*scale + 0.5, one FFMA

#pragma unroll
    for (int k = 0; k < V8_PER_THREAD; k++) {
        const long off = base + (long)(k * THREADS + tid) * 8;
        float xv[8], qv[8];
        ldg256(in + off, xv);
#pragma unroll
        for (int e = 0; e < 8; e++) {
            float x = xv[e];
            // idx = floor((x-mn)*scale + 0.5), clamped; provably in {r, r+1}.
            int idx = __float2int_rd(__fmaf_rn(x, scale, bias));
            idx = min(max(idx, 0), 16);
            float probe = __shfl_sync(0xffffffffu, b_lane, idx);
            // x >= b_idx -> region idx; x < b_idx -> region idx-1.
            // idx=0: probe=b_0=mn <= x always -> r=0 (no underflow).
            int r = idx - ((x < probe) ? 1 : 0);
            qv[e] = __shfl_sync(0xffffffffu, m_lane, r);
        }
        stg256_cs(out + off, qv);
    }
}

extern "C" void kernel_launch(void* const* d_in, const int* in_sizes, int n_in,
                              void* d_out, int out_size) {
    const float* in = (const float*)d_in[0];
    float* out = (float*)d_out;

    dim3 grid(CHUNKS, ROWS);
    minmax_kernel<<<grid, THREADS>>>((const float4*)in);
    quantize_kernel<<<grid, THREADS>>>(in, out);
}

// round 17
// speedup vs baseline: 1.0500x; 1.0500x over previous
#include <cuda_runtime.h>

#define ROWS 48
#define ROW_ELEMS (512 * 512)                  // 262144 elements per (b,c) row
#define CHUNKS 32
#define CHUNK_ELEMS (ROW_ELEMS / CHUNKS)       // 8192
#define THREADS 256
#define V8_PER_THREAD (CHUNK_ELEMS / 8 / THREADS)   // 4 float8 per thread

// Per-(row,chunk) partial min/max. Every slot is written unconditionally by
// minmax_kernel on every call -> no init kernel, no atomics, deterministic.
__device__ float g_pmin[ROWS][CHUNKS];
__device__ float g_pmax[ROWS][CHUNKS];

// 256-bit global load (sm_100a): 8 floats in one LDG.
__device__ __forceinline__ void ldg256(const float* p, float* a) {
    asm volatile("ld.global.nc.v8.f32 {%0,%1,%2,%3,%4,%5,%6,%7}, [%8];"
                 : "=f"(a[0]), "=f"(a[1]), "=f"(a[2]), "=f"(a[3]),
                   "=f"(a[4]), "=f"(a[5]), "=f"(a[6]), "=f"(a[7])
                 : "l"(p));
}
// 256-bit streaming store (evict-first: output is write-once, keep input in L2).
__device__ __forceinline__ void stg256_cs(float* p, const float* a) {
    asm volatile("st.global.cs.v8.f32 [%0], {%1,%2,%3,%4,%5,%6,%7,%8};"
                 :: "l"(p),
                    "f"(a[0]), "f"(a[1]), "f"(a[2]), "f"(a[3]),
                    "f"(a[4]), "f"(a[5]), "f"(a[6]), "f"(a[7])
                 : "memory");
}

__global__ void __launch_bounds__(THREADS, 8) minmax_kernel(const float* __restrict__ in) {
    const int row = blockIdx.y;
    const int chunk = blockIdx.x;
    const long base = (long)row * ROW_ELEMS + (long)chunk * CHUNK_ELEMS;
    const int tid = threadIdx.x;

    float mn = 3.402823466e+38f;
    float mx = -3.402823466e+38f;

#pragma unroll
    for (int k = 0; k < V8_PER_THREAD; k++) {
        float a[8];
        ldg256(in + base + (long)(k * THREADS + tid) * 8, a);
#pragma unroll
        for (int e = 0; e < 8; e++) {
            mn = fminf(mn, a[e]);
            mx = fmaxf(mx, a[e]);
        }
    }

#pragma unroll
    for (int o = 16; o > 0; o >>= 1) {
        mn = fminf(mn, __shfl_xor_sync(0xffffffffu, mn, o));
        mx = fmaxf(mx, __shfl_xor_sync(0xffffffffu, mx, o));
    }

    __shared__ float smn[THREADS / 32];
    __shared__ float smx[THREADS / 32];
    if ((tid & 31) == 0) {
        smn[tid >> 5] = mn;
        smx[tid >> 5] = mx;
    }
    __syncthreads();

    if (tid == 0) {
        float bmn = smn[0], bmx = smx[0];
#pragma unroll
        for (int w = 1; w < THREADS / 32; w++) {
            bmn = fminf(bmn, smn[w]);
            bmx = fmaxf(bmx, smx[w]);
        }
        g_pmin[row][chunk] = bmn;
        g_pmax[row][chunk] = bmx;
    }
}

// Reference-exact bound: b_j = fl32( mn + fl32( d * (j/16) ) ), j/16 exact.
// Exact-rounding intrinsics block fma contraction (must match JAX bit-for-bit).
__device__ __forceinline__ float bound_j(float mn, float d, int j) {
    return __fadd_rn(mn, __fmul_rn(d, (float)j * 0.0625f));
}
// Reference-exact mid: m_j = fl32( 0.5 * fl32( b_j + b_{j+1} ) ).
__device__ __forceinline__ float mid_j(float mn, float d, int j) {
    return __fmul_rn(0.5f, __fadd_rn(bound_j(mn, d, j), bound_j(mn, d, j + 1)));
}

__global__ void __launch_bounds__(THREADS, 8) quantize_kernel(const float* __restrict__ in,
                                                              float* __restrict__ out) {
    const int row = blockIdx.y;
    const int chunk = blockIdx.x;
    const long base = (long)row * ROW_ELEMS + (long)chunk * CHUNK_ELEMS;
    const int tid = threadIdx.x;
    const int lane = tid & 31;

    // One warp reduces the 32 partials; broadcast via 2 smem floats.
    __shared__ float s_mn, s_mx;
    if (tid < 32) {
        float v1 = g_pmin[row][tid];
        float v2 = g_pmax[row][tid];
#pragma unroll
        for (int o = 16; o > 0; o >>= 1) {
            v1 = fminf(v1, __shfl_xor_sync(0xffffffffu, v1, o));
            v2 = fmaxf(v2, __shfl_xor_sync(0xffffffffu, v2, o));
        }
        if (tid == 0) { s_mn = v1; s_mx = v2; }
    }
    __syncthreads();

    const float mn = s_mn;
    const float mx = s_mx;
    const float d = __fadd_rn(mx, -mn);  // mx >= mn

    // Degenerate test, matching float32 reference arithmetic:
    // robust_eps = 4 * FLT_EPSILON; deg = d <= robust_eps + 1e-5 * |mx|
    const float thresh = __fadd_rn(4.76837158203125e-07f, __fmul_rn(1e-5f, fabsf(mx)));
    if (d <= thresh) {
        float q[8];
#pragma unroll
        for (int e = 0; e < 8; e++) q[e] = mn;
#pragma unroll
        for (int k = 0; k < V8_PER_THREAD; k++) {
            stg256_cs(out + base + (long)(k * THREADS + tid) * 8, q);
        }
        return;
    }

    // Warp-register tables (R14 scheme, best measured): lane L holds b_L and m_L.
    //   b_L = bound_L for L<=15, +INF for L>=16  (idx=16 -> probe INF -> r=15)
    //   m_L = mid_L   for L<=15
    const float b_lane = (lane <= 15) ? bound_j(mn, d, lane)
                                      : __int_as_float(0x7f800000);
    const float m_lane = mid_j(mn, d, (lane <= 15) ? lane : 15);

    const float scale = 16.0f / d;
    const float bias = __fmaf_rn(-mn, scale, 0.5f);  // (x-mn)*scale + 0.5, one FFMA

#pragma unroll
    for (int k = 0; k < V8_PER_THREAD; k++) {
        const long off = base + (long)(k * THREADS + tid) * 8;
        float xv[8], qv[8];
        ldg256(in + off, xv);
#pragma unroll
        for (int e = 0; e < 8; e++) {
            float x = xv[e];
            // idx = floor((x-mn)*scale + 0.5), clamped; provably in {r, r+1}.
            int idx = __float2int_rd(__fmaf_rn(x, scale, bias));
            idx = min(max(idx, 0), 16);
            float probe = __shfl_sync(0xffffffffu, b_lane, idx);
            // x >= b_idx -> region idx; x < b_idx -> region idx-1.
            // idx=0: probe=b_0=mn <= x always -> r=0 (no underflow).
            int r = idx - ((x < probe) ? 1 : 0);
            qv[e] = __shfl_sync(0xffffffffu, m_lane, r);
        }
        stg256_cs(out + off, qv);
    }
}

extern "C" void kernel_launch(void* const* d_in, const int* in_sizes, int n_in,
                              void* d_out, int out_size) {
    const float* in = (const float*)d_in[0];
    float* out = (float*)d_out;

    dim3 grid(CHUNKS, ROWS);
    minmax_kernel<<<grid, THREADS>>>(in);
    quantize_kernel<<<grid, THREADS>>>(in, out);
}